// round 1
// baseline (speedup 1.0000x reference)
#include <cuda_runtime.h>
#include <math.h>

#define N_NODES 8192
#define FIN 128
#define FOUT 64
#define LRELU_ALPHA 0.2f

// Scratch (device globals — no allocation allowed in kernel_launch)
__device__ float g_Wh[N_NODES * FOUT];   // 2 MB
__device__ float g_s1[N_NODES];
__device__ float g_s2[N_NODES];

// ---------------------------------------------------------------------------
// Kernel 1: Wh = h @ W ; s1 = Wh@a1 ; s2 = Wh@a2.  One block (64 thr) per row.
// ---------------------------------------------------------------------------
__global__ __launch_bounds__(64) void wh_kernel(const float* __restrict__ h,
                                                const float* __restrict__ W,
                                                const float* __restrict__ a) {
    __shared__ float sh[FIN];
    __shared__ float red1[2], red2[2];
    const int i = blockIdx.x;
    const int f = threadIdx.x;

    // load h row (128 floats) with 64 threads
    sh[f]      = h[(size_t)i * FIN + f];
    sh[f + 64] = h[(size_t)i * FIN + f + 64];
    __syncthreads();

    float acc = 0.f;
#pragma unroll
    for (int k = 0; k < FIN; k++)
        acc = fmaf(sh[k], W[k * FOUT + f], acc);

    g_Wh[(size_t)i * FOUT + f] = acc;

    float v1 = acc * a[f];         // a1[f]
    float v2 = acc * a[FOUT + f];  // a2[f]
#pragma unroll
    for (int o = 16; o > 0; o >>= 1) {
        v1 += __shfl_xor_sync(0xFFFFFFFFu, v1, o);
        v2 += __shfl_xor_sync(0xFFFFFFFFu, v2, o);
    }
    if ((f & 31) == 0) { red1[f >> 5] = v1; red2[f >> 5] = v2; }
    __syncthreads();
    if (f == 0) {
        g_s1[i] = red1[0] + red1[1];
        g_s2[i] = red2[0] + red2[1];
    }
}

// ---------------------------------------------------------------------------
// Kernel 2: fused masked-leakyrelu-softmax + attention@Wh + ELU.
// One warp per output row i; 8 rows per block (warps share Wh stream -> L1 reuse).
// Online (flash) softmax, float2 accumulator = 2 output features per lane.
// ---------------------------------------------------------------------------
__global__ __launch_bounds__(256) void attn_kernel(const int*   __restrict__ adj,
                                                   const float* __restrict__ efeat,
                                                   const float* __restrict__ a,
                                                   float*       __restrict__ out) {
    const int warp = threadIdx.x >> 5;
    const int lane = threadIdx.x & 31;
    const int i = blockIdx.x * 8 + warp;

    const float ae  = a[2 * FOUT];
    const float s1i = g_s1[i];
    const int*   adjrow = adj   + (size_t)i * N_NODES;
    const float* efrow  = efeat + (size_t)i * N_NODES;
    const float2* wh2   = (const float2*)g_Wh;  // [j][32] float2 view

    float  m = -1e30f;   // running max
    float  l = 0.f;      // per-lane partial denom
    float2 acc = make_float2(0.f, 0.f);

    for (int jb = 0; jb < N_NODES; jb += 32) {
        const int j = jb + lane;
        const int   av = adjrow[j];
        const float ef = efrow[j];

        float e = fmaf(ef, ae, s1i + g_s2[j]);
        e = (e > 0.f) ? e : LRELU_ALPHA * e;      // LeakyReLU
        const bool valid = (av > 0);
        float ec = valid ? e : -1e30f;

        // warp max of this chunk
        float cmax = ec;
#pragma unroll
        for (int o = 16; o > 0; o >>= 1)
            cmax = fmaxf(cmax, __shfl_xor_sync(0xFFFFFFFFu, cmax, o));
        if (cmax <= -1e29f) continue;             // whole chunk masked

        const float nm    = fmaxf(m, cmax);
        const float scale = __expf(m - nm);       // underflows to 0 on first chunk
        m = nm;

        const float p = valid ? __expf(e - nm) : 0.f;
        l = fmaf(l, scale, p);
        acc.x *= scale;
        acc.y *= scale;

        const float2* wbase = wh2 + (size_t)jb * 32 + lane;
#pragma unroll
        for (int jj = 0; jj < 32; jj++) {
            const float pj = __shfl_sync(0xFFFFFFFFu, p, jj);
            if (pj != 0.f) {                      // warp-uniform: skip masked j
                const float2 w = wbase[jj * 32];
                acc.x = fmaf(pj, w.x, acc.x);
                acc.y = fmaf(pj, w.y, acc.y);
            }
        }
    }

    // denominator: sum per-lane partials across warp
    float lt = l;
#pragma unroll
    for (int o = 16; o > 0; o >>= 1)
        lt += __shfl_xor_sync(0xFFFFFFFFu, lt, o);
    const float inv = 1.f / lt;

    float ox = acc.x * inv;
    float oy = acc.y * inv;
    ox = (ox > 0.f) ? ox : expm1f(ox);            // ELU (alpha = 1)
    oy = (oy > 0.f) ? oy : expm1f(oy);

    ((float2*)out)[(size_t)i * 32 + lane] = make_float2(ox, oy);
}

// ---------------------------------------------------------------------------
extern "C" void kernel_launch(void* const* d_in, const int* in_sizes, int n_in,
                              void* d_out, int out_size) {
    const float* h     = (const float*)d_in[0];   // [8192,128]
    const int*   adj   = (const int*)  d_in[1];   // [8192,8192]
    const float* efeat = (const float*)d_in[2];   // [8192,8192]
    const float* W     = (const float*)d_in[3];   // [128,64]
    const float* a     = (const float*)d_in[4];   // [129,1]
    float* out = (float*)d_out;                   // [8192,64]

    wh_kernel<<<N_NODES, 64>>>(h, W, a);
    attn_kernel<<<N_NODES / 8, 256>>>(adj, efeat, a, out);
}

// round 3
// speedup vs baseline: 1.4989x; 1.4989x over previous
#include <cuda_runtime.h>
#include <math.h>
#include <cstdint>

#define N_NODES 8192
#define FIN 128
#define FOUT 64
#define NB 80              // 64 features + ones col + 15 pad
#define TILE_M 64
#define NTILES 64          // 8192 / 128 j-cols per tile
#define LRELU_ALPHA 0.2f

// ---------------- device scratch (no allocation allowed) -------------------
__device__ __align__(256) float g_Whb[N_NODES * NB];   // tf32-rounded Wh | 1 | 0-pad
__device__ float g_s1[N_NODES];
__device__ float g_s2[N_NODES];

// ---------------- SMEM layout ------------------------------------------------
// P tile: 64 rows x 132 floats (stride pad)      = 33792 B
// B tile: 64 pair-rows x 85 pairs x 8 B          = 43520 B
#define P_STRIDE 132
#define B_STRIDE 85
#define OFF_SDEN 0
#define OFF_P0   1024
#define OFF_B0   (1024 + 33792)
#define OFF_P1   (OFF_B0 + 43520)
#define OFF_B1   (OFF_P1 + 33792)
#define SMEM_BYTES (OFF_B1 + 43520)   // 155648

// ---------------- helpers ----------------------------------------------------
__device__ __forceinline__ uint32_t smem_u32(const void* p) {
    uint32_t a;
    asm("{ .reg .u64 t; cvta.to.shared.u64 t, %1; cvt.u32.u64 %0, t; }" : "=r"(a) : "l"(p));
    return a;
}
__device__ __forceinline__ uint32_t f2tf32(float x) {
    uint32_t u;
    asm("cvt.rna.tf32.f32 %0, %1;" : "=r"(u) : "f"(x));
    return u;
}
__device__ __forceinline__ uint32_t lds32(uint32_t a) {
    uint32_t v; asm("ld.shared.b32 %0, [%1];" : "=r"(v) : "r"(a)); return v;
}
__device__ __forceinline__ uint2 lds64(uint32_t a) {
    uint2 v; asm("ld.shared.v2.b32 {%0,%1}, [%2];" : "=r"(v.x), "=r"(v.y) : "r"(a)); return v;
}
__device__ __forceinline__ void sts32(uint32_t a, uint32_t v) {
    asm volatile("st.shared.b32 [%0], %1;" :: "r"(a), "r"(v) : "memory");
}
__device__ __forceinline__ void sts128(uint32_t a, uint32_t v0, uint32_t v1, uint32_t v2, uint32_t v3) {
    asm volatile("st.shared.v4.b32 [%0], {%1,%2,%3,%4};" :: "r"(a), "r"(v0), "r"(v1), "r"(v2), "r"(v3) : "memory");
}
#define BAR_SYNC(id)   asm volatile("bar.sync %0, 256;"   :: "r"(id) : "memory")
#define BAR_ARRIVE(id) asm volatile("bar.arrive %0, 256;" :: "r"(id) : "memory")

__device__ __forceinline__ void mma_tf32(float& c0, float& c1, float& c2, float& c3,
                                         uint32_t a0, uint32_t a1, uint32_t a2, uint32_t a3,
                                         uint32_t b0, uint32_t b1) {
    asm("mma.sync.aligned.m16n8k8.row.col.f32.tf32.tf32.f32 "
        "{%0,%1,%2,%3},{%4,%5,%6,%7},{%8,%9},{%0,%1,%2,%3};"
        : "+f"(c0), "+f"(c1), "+f"(c2), "+f"(c3)
        : "r"(a0), "r"(a1), "r"(a2), "r"(a3), "r"(b0), "r"(b1));
}

// ---------------------------------------------------------------------------
// Kernel 1: Wh = h@W ; store tf32-rounded + ones col into g_Whb; s1, s2 fp32.
// ---------------------------------------------------------------------------
__global__ __launch_bounds__(64) void wh_kernel(const float* __restrict__ h,
                                                const float* __restrict__ W,
                                                const float* __restrict__ a) {
    __shared__ float sh[FIN];
    __shared__ float red1[2], red2[2];
    const int i = blockIdx.x;
    const int f = threadIdx.x;

    sh[f]      = h[(size_t)i * FIN + f];
    sh[f + 64] = h[(size_t)i * FIN + f + 64];
    __syncthreads();

    float acc = 0.f;
#pragma unroll
    for (int k = 0; k < FIN; k++)
        acc = fmaf(sh[k], W[k * FOUT + f], acc);

    g_Whb[(size_t)i * NB + f] = __uint_as_float(f2tf32(acc));
    if (f == 0) g_Whb[(size_t)i * NB + 64] = 1.0f;          // denominator column
    if (f >= 1 && f < 16) g_Whb[(size_t)i * NB + 64 + f] = 0.0f;

    float v1 = acc * a[f];
    float v2 = acc * a[FOUT + f];
#pragma unroll
    for (int o = 16; o > 0; o >>= 1) {
        v1 += __shfl_xor_sync(0xFFFFFFFFu, v1, o);
        v2 += __shfl_xor_sync(0xFFFFFFFFu, v2, o);
    }
    if ((f & 31) == 0) { red1[f >> 5] = v1; red2[f >> 5] = v2; }
    __syncthreads();
    if (f == 0) {
        g_s1[i] = red1[0] + red1[1];
        g_s2[i] = red2[0] + red2[1];
    }
}

// ---------------------------------------------------------------------------
// Kernel 2: warp-specialized producer/consumer.
//  warps 0-3 (consumers): mma.sync tf32, each owns m32 x n40 of D[64 x 80].
//  warps 4-7 (producers): build P (masked exp) + B (Whb slice) SMEM tiles.
// ---------------------------------------------------------------------------
__global__ __launch_bounds__(256, 1) void attn_mma_kernel(const int*   __restrict__ adj,
                                                          const float* __restrict__ efeat,
                                                          const float* __restrict__ a,
                                                          float*       __restrict__ out) {
    extern __shared__ char smem[];
    const uint32_t sbase = smem_u32(smem);
    const int tid  = threadIdx.x;
    const int wid  = tid >> 5;
    const int lane = tid & 31;
    const int i0   = blockIdx.x * TILE_M;

    const uint32_t pOff[2] = { sbase + OFF_P0, sbase + OFF_P1 };
    const uint32_t bOff[2] = { sbase + OFF_B0, sbase + OFF_B1 };

    if (wid < 4) {
        // ================= CONSUMER =================
        const int g    = lane >> 2;
        const int tig  = lane & 3;
        const int mhalf = wid & 1;
        const int nhalf = wid >> 1;

        // A: P(r, c) at pbase + (r*132 + c)*4 ; rows r0=mhalf*32+mblk*16+g (+8)
        const uint32_t aoff0 = (uint32_t)((mhalf * 32 + g) * P_STRIDE + tig) * 4;
        const uint32_t aoff1 = aoff0 + 16u * P_STRIDE * 4;
        // B: pair (k=ks*8+tig, +4) at bbase + ((ks*4+tig)*85 + n)*8
        const uint32_t boff0 = (uint32_t)(tig * B_STRIDE + nhalf * 40 + g) * 8;

        float C[2][5][4];
#pragma unroll
        for (int m = 0; m < 2; m++)
#pragma unroll
            for (int n = 0; n < 5; n++)
#pragma unroll
                for (int q = 0; q < 4; q++) C[m][n][q] = 0.f;

        for (int t = 0; t < NTILES; t++) {
            const int b = t & 1;
            BAR_SYNC(1 + b);                      // wait FULL
            const uint32_t pb = pOff[b], bb = bOff[b];
#pragma unroll
            for (int ks = 0; ks < 16; ks++) {
                uint32_t A0[4], A1[4];
                const uint32_t pa0 = pb + aoff0 + (uint32_t)ks * 32;
                const uint32_t pa1 = pb + aoff1 + (uint32_t)ks * 32;
                A0[0] = lds32(pa0);            A0[2] = lds32(pa0 + 16);
                A0[1] = lds32(pa0 + 4224);     A0[3] = lds32(pa0 + 4224 + 16); // +8 rows
                A1[0] = lds32(pa1);            A1[2] = lds32(pa1 + 16);
                A1[1] = lds32(pa1 + 4224);     A1[3] = lds32(pa1 + 4224 + 16);
                const uint32_t bbase = bb + boff0 + (uint32_t)ks * (4 * B_STRIDE * 8);
#pragma unroll
                for (int nf = 0; nf < 5; nf++) {
                    const uint2 bf = lds64(bbase + (uint32_t)nf * 64);
                    mma_tf32(C[0][nf][0], C[0][nf][1], C[0][nf][2], C[0][nf][3],
                             A0[0], A0[1], A0[2], A0[3], bf.x, bf.y);
                    mma_tf32(C[1][nf][0], C[1][nf][1], C[1][nf][2], C[1][nf][3],
                             A1[0], A1[1], A1[2], A1[3], bf.x, bf.y);
                }
            }
            if (t < NTILES - 2) BAR_ARRIVE(3 + b);   // signal EMPTY
        }

        // ---------- epilogue ----------
        float* sden = (float*)smem;               // 64 floats at offset 0
        if (nhalf == 1 && tig == 0) {
            // global col 64 = nf 3, frag col 0 -> c0 (row g), c2 (row g+8)
#pragma unroll
            for (int m = 0; m < 2; m++) {
                const int r = mhalf * 32 + m * 16 + g;
                sden[r]     = C[m][3][0];
                sden[r + 8] = C[m][3][2];
            }
        }
        asm volatile("bar.sync 5, 128;" ::: "memory");

#pragma unroll
        for (int m = 0; m < 2; m++) {
            const int r1 = mhalf * 32 + m * 16 + g;
            const int r2 = r1 + 8;
            const float inv1 = 1.f / sden[r1];
            const float inv2 = 1.f / sden[r2];
#pragma unroll
            for (int nf = 0; nf < 5; nf++) {
                const int gcol = nhalf * 40 + nf * 8 + 2 * tig;
                if (gcol < 64) {
                    float v0 = C[m][nf][0] * inv1, v1 = C[m][nf][1] * inv1;
                    float v2 = C[m][nf][2] * inv2, v3 = C[m][nf][3] * inv2;
                    v0 = (v0 > 0.f) ? v0 : expm1f(v0);
                    v1 = (v1 > 0.f) ? v1 : expm1f(v1);
                    v2 = (v2 > 0.f) ? v2 : expm1f(v2);
                    v3 = (v3 > 0.f) ? v3 : expm1f(v3);
                    *(float2*)(out + (size_t)(i0 + r1) * FOUT + gcol) = make_float2(v0, v1);
                    *(float2*)(out + (size_t)(i0 + r2) * FOUT + gcol) = make_float2(v2, v3);
                }
            }
        }
    } else {
        // ================= PRODUCER =================
        const int ptid = tid - 128;               // 0..127
        const int rb   = ptid >> 2;               // 0..31
        const int cq   = ptid & 3;                // col quarter
        const int col0 = cq * 32;
        const float ae = a[2 * FOUT];

        // B writer coords: row j = jb + ptid
        const int R    = ((ptid >> 3) << 2) + (ptid & 3);
        const int sel  = (ptid >> 2) & 1;
        const uint32_t bwr_base = (uint32_t)(R * B_STRIDE) * 8 + (uint32_t)sel * 4;

        for (int t = 0; t < NTILES; t++) {
            const int b  = t & 1;
            const int jb = t << 7;
            if (t >= 2) BAR_SYNC(3 + b);          // wait EMPTY

            // ---- B tile: row jb+ptid of g_Whb (80 tf32 floats) ----
            {
                const float4* wrow = (const float4*)(g_Whb + (size_t)(jb + ptid) * NB);
                const uint32_t dst = bOff[b] + bwr_base;
#pragma unroll
                for (int n4 = 0; n4 < 20; n4++) {
                    const float4 v = wrow[n4];
                    const uint32_t o = dst + (uint32_t)n4 * 32;
                    sts32(o,      __float_as_uint(v.x));
                    sts32(o + 8,  __float_as_uint(v.y));
                    sts32(o + 16, __float_as_uint(v.z));
                    sts32(o + 24, __float_as_uint(v.w));
                }
            }

            // ---- s2 slice for this col quarter ----
            float4 s2c[8];
            const float4* s2p = (const float4*)(g_s2 + jb + col0);
#pragma unroll
            for (int k = 0; k < 8; k++) s2c[k] = s2p[k];

            // ---- P tile: 2 passes x 8 float4 per thread ----
#pragma unroll
            for (int pass = 0; pass < 2; pass++) {
                const int r    = rb + pass * 32;
                const int grow = i0 + r;
                const float s1 = g_s1[grow];
                const int4*   pa = (const int4*)  (adj   + (size_t)grow * N_NODES + jb + col0);
                const float4* pe = (const float4*)(efeat + (size_t)grow * N_NODES + jb + col0);
                const uint32_t prow = pOff[b] + (uint32_t)(r * P_STRIDE + col0) * 4;
#pragma unroll
                for (int k = 0; k < 8; k++) {
                    const int4   av = pa[k];
                    const float4 ev = pe[k];
                    const float4 sv = s2c[k];
                    float e0 = fmaf(ev.x, ae, s1 + sv.x);
                    float e1 = fmaf(ev.y, ae, s1 + sv.y);
                    float e2 = fmaf(ev.z, ae, s1 + sv.z);
                    float e3 = fmaf(ev.w, ae, s1 + sv.w);
                    e0 = fmaxf(e0, LRELU_ALPHA * e0);
                    e1 = fmaxf(e1, LRELU_ALPHA * e1);
                    e2 = fmaxf(e2, LRELU_ALPHA * e2);
                    e3 = fmaxf(e3, LRELU_ALPHA * e3);
                    const uint32_t u0 = (av.x > 0) ? f2tf32(__expf(e0)) : 0u;
                    const uint32_t u1 = (av.y > 0) ? f2tf32(__expf(e1)) : 0u;
                    const uint32_t u2 = (av.z > 0) ? f2tf32(__expf(e2)) : 0u;
                    const uint32_t u3 = (av.w > 0) ? f2tf32(__expf(e3)) : 0u;
                    sts128(prow + (uint32_t)k * 16, u0, u1, u2, u3);
                }
            }
            BAR_ARRIVE(1 + b);                    // signal FULL
        }
    }
}

// ---------------------------------------------------------------------------
extern "C" void kernel_launch(void* const* d_in, const int* in_sizes, int n_in,
                              void* d_out, int out_size) {
    const float* h     = (const float*)d_in[0];   // [8192,128]
    const int*   adj   = (const int*)  d_in[1];   // [8192,8192]
    const float* efeat = (const float*)d_in[2];   // [8192,8192]
    const float* W     = (const float*)d_in[3];   // [128,64]
    const float* a     = (const float*)d_in[4];   // [129,1]
    float* out = (float*)d_out;                   // [8192,64]

    cudaFuncSetAttribute(attn_mma_kernel,
                         cudaFuncAttributeMaxDynamicSharedMemorySize, SMEM_BYTES);

    wh_kernel<<<N_NODES, 64>>>(h, W, a);
    attn_mma_kernel<<<N_NODES / TILE_M, 256, SMEM_BYTES>>>(adj, efeat, a, out);
}

// round 4
// speedup vs baseline: 2.4569x; 1.6392x over previous
#include <cuda_runtime.h>
#include <math.h>
#include <cstdint>

#define N_NODES 8192
#define FIN 128
#define FOUT 64
#define NB 72              // 64 feats + ones col + 7 pad
#define TILE_M 64
#define JTILES 32          // j-tiles per CTA (j-split = 2)
#define NSTAGE 3
#define LRELU_ALPHA 0.2f

#define P_STRIDE 132
#define P_BYTES (TILE_M * P_STRIDE * 4)     // 33792
#define SMEM_BYTES (NSTAGE * P_BYTES)       // 101376
#define PART_STRIDE 66

// ---------------- device scratch (no allocation allowed) -------------------
__device__ __align__(256) float g_Bpack[1024 * (NB * 8)]; // frag-packed Whb, 2.36 MB
__device__ __align__(256) float g_part[256 * 64 * PART_STRIDE]; // partials, 4.3 MB
__device__ float g_s1[N_NODES];
__device__ float g_s2[N_NODES];

// ---------------- helpers ----------------------------------------------------
__device__ __forceinline__ uint32_t smem_u32(const void* p) {
    uint32_t a;
    asm("{ .reg .u64 t; cvta.to.shared.u64 t, %1; cvt.u32.u64 %0, t; }" : "=r"(a) : "l"(p));
    return a;
}
__device__ __forceinline__ uint32_t f2tf32(float x) {
    uint32_t u;
    asm("cvt.rna.tf32.f32 %0, %1;" : "=r"(u) : "f"(x));
    return u;
}
__device__ __forceinline__ uint32_t lds32(uint32_t a) {
    uint32_t v; asm("ld.shared.b32 %0, [%1];" : "=r"(v) : "r"(a)); return v;
}
__device__ __forceinline__ void sts128(uint32_t a, uint32_t v0, uint32_t v1, uint32_t v2, uint32_t v3) {
    asm volatile("st.shared.v4.b32 [%0], {%1,%2,%3,%4};" :: "r"(a), "r"(v0), "r"(v1), "r"(v2), "r"(v3) : "memory");
}
#define BAR_SYNC(id)   asm volatile("bar.sync %0, 256;"   :: "r"(id) : "memory")
#define BAR_ARRIVE(id) asm volatile("bar.arrive %0, 256;" :: "r"(id) : "memory")

__device__ __forceinline__ void mma_tf32(float* c,
                                         uint32_t a0, uint32_t a1, uint32_t a2, uint32_t a3,
                                         uint32_t b0, uint32_t b1) {
    asm("mma.sync.aligned.m16n8k8.row.col.f32.tf32.tf32.f32 "
        "{%0,%1,%2,%3},{%4,%5,%6,%7},{%8,%9},{%0,%1,%2,%3};"
        : "+f"(c[0]), "+f"(c[1]), "+f"(c[2]), "+f"(c[3])
        : "r"(a0), "r"(a1), "r"(a2), "r"(a3), "r"(b0), "r"(b1));
}

// ---------------------------------------------------------------------------
// Kernel 1: Wh = h@W -> g_Bpack (mma B-fragment order, tf32) ; s1, s2.
// Pack layout: [ksgrp = jt*16+ks][n][tig][sel], elem = float, stride n: 8.
//   j = jt*128 + ks*8 + sel*4 + tig
// ---------------------------------------------------------------------------
__global__ __launch_bounds__(64) void wh_kernel(const float* __restrict__ h,
                                                const float* __restrict__ W,
                                                const float* __restrict__ a) {
    __shared__ float sh[FIN];
    __shared__ float red1[2], red2[2];
    const int i = blockIdx.x;
    const int f = threadIdx.x;

    sh[f]      = h[(size_t)i * FIN + f];
    sh[f + 64] = h[(size_t)i * FIN + f + 64];
    __syncthreads();

    float acc = 0.f;
#pragma unroll
    for (int k = 0; k < FIN; k++)
        acc = fmaf(sh[k], W[k * FOUT + f], acc);

    const int jt  = i >> 7;
    const int ks  = (i >> 3) & 15;
    const int sel = (i >> 2) & 1;
    const int tig = i & 3;
    const size_t base = (size_t)(jt * 16 + ks) * (NB * 8) + tig * 2 + sel;
    g_Bpack[base + (size_t)f * 8] = __uint_as_float(f2tf32(acc));
    if (f < 8)
        g_Bpack[base + (size_t)(64 + f) * 8] = (f == 0) ? 1.0f : 0.0f;

    float v1 = acc * a[f];
    float v2 = acc * a[FOUT + f];
#pragma unroll
    for (int o = 16; o > 0; o >>= 1) {
        v1 += __shfl_xor_sync(0xFFFFFFFFu, v1, o);
        v2 += __shfl_xor_sync(0xFFFFFFFFu, v2, o);
    }
    if ((f & 31) == 0) { red1[f >> 5] = v1; red2[f >> 5] = v2; }
    __syncthreads();
    if (f == 0) {
        g_s1[i] = red1[0] + red1[1];
        g_s2[i] = red2[0] + red2[1];
    }
}

// ---------------------------------------------------------------------------
// Consumer: templated on NF (5 for n 0..39, 4 for n 40..71) and NHALF.
// ---------------------------------------------------------------------------
template <int NF, int NHALF>
__device__ __forceinline__ void consumer_loop(uint32_t sbase, int mhalf, int lane,
                                              int half, int cta) {
    const int g   = lane >> 2;
    const int tig = lane & 3;
    const uint32_t aoff0 = (uint32_t)((mhalf * 32 + g) * P_STRIDE + tig) * 4;
    const float* __restrict__ bbase = g_Bpack + (NHALF * 40 + g) * 8 + tig * 2
                                    + (size_t)(half * JTILES) * 16 * (NB * 8);

    float C[2][NF][4];
#pragma unroll
    for (int m = 0; m < 2; m++)
#pragma unroll
        for (int n = 0; n < NF; n++)
#pragma unroll
            for (int q = 0; q < 4; q++) C[m][n][q] = 0.f;

    int s = 0;
    for (int t = 0; t < JTILES; t++) {
        BAR_SYNC(1 + s);
        const uint32_t pb = sbase + (uint32_t)s * P_BYTES;
        const float* __restrict__ kb = bbase + (size_t)t * 16 * (NB * 8);
#pragma unroll
        for (int ks = 0; ks < 16; ks++) {
            const uint32_t pa0 = pb + aoff0 + (uint32_t)ks * 32;
            const uint32_t pa1 = pa0 + 16u * P_STRIDE * 4;
            uint32_t A0[4], A1[4];
            A0[0] = lds32(pa0);        A0[1] = lds32(pa0 + 8u * P_STRIDE * 4);
            A0[2] = lds32(pa0 + 16);   A0[3] = lds32(pa0 + 8u * P_STRIDE * 4 + 16);
            A1[0] = lds32(pa1);        A1[1] = lds32(pa1 + 8u * P_STRIDE * 4);
            A1[2] = lds32(pa1 + 16);   A1[3] = lds32(pa1 + 8u * P_STRIDE * 4 + 16);
            const float* bp = kb + ks * (NB * 8);
#pragma unroll
            for (int nf = 0; nf < NF; nf++) {
                const float2 bf = *(const float2*)(bp + nf * 64);
                const uint32_t b0 = __float_as_uint(bf.x);
                const uint32_t b1 = __float_as_uint(bf.y);
                mma_tf32(C[0][nf], A0[0], A0[1], A0[2], A0[3], b0, b1);
                mma_tf32(C[1][nf], A1[0], A1[1], A1[2], A1[3], b0, b1);
            }
        }
        if (t < JTILES - NSTAGE) BAR_ARRIVE(4 + s);
        s = (s == NSTAGE - 1) ? 0 : s + 1;
    }

    // store partials (numerator cols 0..63, denominator col 64)
    float* pbase = g_part + (size_t)cta * 64 * PART_STRIDE;
#pragma unroll
    for (int m = 0; m < 2; m++) {
        const int r1 = mhalf * 32 + m * 16 + g;
        float* prow1 = pbase + r1 * PART_STRIDE;
        float* prow2 = prow1 + 8 * PART_STRIDE;
#pragma unroll
        for (int nf = 0; nf < NF; nf++) {
            const int gcol = NHALF * 40 + nf * 8 + 2 * tig;
            if (gcol < 64) {
                *(float2*)(prow1 + gcol) = make_float2(C[m][nf][0], C[m][nf][1]);
                *(float2*)(prow2 + gcol) = make_float2(C[m][nf][2], C[m][nf][3]);
            } else if (gcol == 64) {
                prow1[64] = C[m][nf][0];
                prow2[64] = C[m][nf][2];
            }
        }
    }
}

// ---------------------------------------------------------------------------
// Kernel 2: warp-specialized.  grid = 256 (row-block x j-half), 2 CTAs/SM.
//  warps 0-3: mma consumers.  warps 4-7: P-tile producers (masked exp).
// ---------------------------------------------------------------------------
__global__ __launch_bounds__(256, 2) void attn_mma_kernel(const int*   __restrict__ adj,
                                                          const float* __restrict__ efeat,
                                                          const float* __restrict__ a) {
    extern __shared__ char smem[];
    const uint32_t sbase = smem_u32(smem);
    const int tid  = threadIdx.x;
    const int wid  = tid >> 5;
    const int lane = tid & 31;
    const int cta  = blockIdx.x;
    const int i0   = (cta >> 1) * TILE_M;
    const int half = cta & 1;

    if (wid < 4) {
        const int mhalf = wid & 1;
        if ((wid >> 1) == 0) consumer_loop<5, 0>(sbase, mhalf, lane, half, cta);
        else                 consumer_loop<4, 1>(sbase, mhalf, lane, half, cta);
    } else {
        // ================= PRODUCER =================
        const int ptid = tid - 128;
        const int rb   = ptid >> 2;
        const int col0 = (ptid & 3) * 32;
        const float ae = a[2 * FOUT];

        int s = 0;
        for (int t = 0; t < JTILES; t++) {
            const int jb = half * 4096 + (t << 7);
            if (t >= NSTAGE) BAR_SYNC(4 + s);
            const float4* __restrict__ s2p = (const float4*)(g_s2 + jb + col0);
#pragma unroll
            for (int pass = 0; pass < 2; pass++) {
                const int r    = rb + pass * 32;
                const int grow = i0 + r;
                const float s1 = g_s1[grow];
                const int4*   __restrict__ pa = (const int4*)  (adj   + (size_t)grow * N_NODES + jb + col0);
                const float4* __restrict__ pe = (const float4*)(efeat + (size_t)grow * N_NODES + jb + col0);
                const uint32_t prow = sbase + (uint32_t)s * P_BYTES
                                    + (uint32_t)(r * P_STRIDE + col0) * 4;
#pragma unroll
                for (int k = 0; k < 8; k++) {
                    const int4   av = pa[k];
                    const float4 ev = pe[k];
                    const float4 sv = s2p[k];
                    float e0 = fmaf(ev.x, ae, s1 + sv.x);
                    float e1 = fmaf(ev.y, ae, s1 + sv.y);
                    float e2 = fmaf(ev.z, ae, s1 + sv.z);
                    float e3 = fmaf(ev.w, ae, s1 + sv.w);
                    e0 = fmaxf(e0, LRELU_ALPHA * e0);
                    e1 = fmaxf(e1, LRELU_ALPHA * e1);
                    e2 = fmaxf(e2, LRELU_ALPHA * e2);
                    e3 = fmaxf(e3, LRELU_ALPHA * e3);
                    const uint32_t u0 = (av.x > 0) ? f2tf32(__expf(e0)) : 0u;
                    const uint32_t u1 = (av.y > 0) ? f2tf32(__expf(e1)) : 0u;
                    const uint32_t u2 = (av.z > 0) ? f2tf32(__expf(e2)) : 0u;
                    const uint32_t u3 = (av.w > 0) ? f2tf32(__expf(e3)) : 0u;
                    sts128(prow + (uint32_t)k * 16, u0, u1, u2, u3);
                }
            }
            BAR_ARRIVE(1 + s);
            s = (s == NSTAGE - 1) ? 0 : s + 1;
        }
    }
}

// ---------------------------------------------------------------------------
// Kernel 3: combine the two j-half partials, divide, ELU, store.
// ---------------------------------------------------------------------------
__global__ __launch_bounds__(256) void combine_kernel(float* __restrict__ out) {
    const int idx = blockIdx.x * 256 + threadIdx.x;   // 8192*32
    const int i   = idx >> 5;
    const int f2  = idx & 31;
    const float* p0 = g_part + ((size_t)(i >> 6) * 2 * 64 + (i & 63)) * PART_STRIDE;
    const float* p1 = p0 + 64 * PART_STRIDE;
    const float inv = 1.f / (p0[64] + p1[64]);
    const float2 a0 = *(const float2*)(p0 + f2 * 2);
    const float2 b0 = *(const float2*)(p1 + f2 * 2);
    float v0 = (a0.x + b0.x) * inv;
    float v1 = (a0.y + b0.y) * inv;
    v0 = (v0 > 0.f) ? v0 : expm1f(v0);
    v1 = (v1 > 0.f) ? v1 : expm1f(v1);
    *(float2*)(out + (size_t)i * FOUT + f2 * 2) = make_float2(v0, v1);
}

// ---------------------------------------------------------------------------
extern "C" void kernel_launch(void* const* d_in, const int* in_sizes, int n_in,
                              void* d_out, int out_size) {
    const float* h     = (const float*)d_in[0];   // [8192,128]
    const int*   adj   = (const int*)  d_in[1];   // [8192,8192]
    const float* efeat = (const float*)d_in[2];   // [8192,8192]
    const float* W     = (const float*)d_in[3];   // [128,64]
    const float* a     = (const float*)d_in[4];   // [129,1]
    float* out = (float*)d_out;                   // [8192,64]

    cudaFuncSetAttribute(attn_mma_kernel,
                         cudaFuncAttributeMaxDynamicSharedMemorySize, SMEM_BYTES);

    wh_kernel<<<N_NODES, 64>>>(h, W, a);
    attn_mma_kernel<<<256, 256, SMEM_BYTES>>>(adj, efeat, a);
    combine_kernel<<<1024, 256>>>(out);
}